// round 10
// baseline (speedup 1.0000x reference)
#include <cuda_runtime.h>

#define NQ 10
#define NT 64            // 2 warps per block = 1 batch element
#define R  16            // amplitudes per thread (4 register bits)

typedef unsigned long long u64;

// ---- packed f32x2 helpers (sm_103a) ----
__device__ __forceinline__ u64 pack2(float x, float y) {
    u64 r; asm("mov.b64 %0, {%1,%2};" : "=l"(r) : "f"(x), "f"(y)); return r;
}
__device__ __forceinline__ void unpack2(u64 v, float& x, float& y) {
    asm("mov.b64 {%0,%1}, %2;" : "=f"(x), "=f"(y) : "l"(v));
}
__device__ __forceinline__ u64 swap2(u64 v) {
    float x, y; unpack2(v, x, y); return pack2(y, x);
}
__device__ __forceinline__ u64 fma2(u64 a, u64 b, u64 c) {
    u64 d; asm("fma.rn.f32x2 %0, %1, %2, %3;" : "=l"(d) : "l"(a), "l"(b), "l"(c)); return d;
}
__device__ __forceinline__ u64 mul2(u64 a, u64 b) {
    u64 d; asm("mul.rn.f32x2 %0, %1, %2;" : "=l"(d) : "l"(a), "l"(b)); return d;
}
__device__ __forceinline__ float2 cmul(float2 a, float2 b) {
    return make_float2(a.x * b.x - a.y * b.y, a.x * b.y + a.y * b.x);
}
// amp *= m, with m pre-packed as mxx=(m.x,m.x), myy=(-m.y,m.y)
__device__ __forceinline__ u64 dmul(u64 amp, u64 mxx, u64 myy) {
    return fma2(mxx, amp, mul2(myy, swap2(amp)));
}
// XOR swizzle on the 1024-u64 block-private region; conflict-free for all
// access patterns below (lane maps are GF(2)-injective).
__device__ __forceinline__ int phys(int i) { return i ^ ((i >> 5) & 31); }

// Lifted RY on register-bit P of the 4-bit reg index (8 pairs).
template<int P>
__device__ __forceinline__ void ry_lift(u64* a, u64 pt, u64 mt)
{
#pragma unroll
    for (int k = 0; k < 8; k++) {
        const int r0 = ((k >> P) << (P + 1)) | (k & ((1 << P) - 1));
        const int r1 = r0 | (1 << P);
        const u64 a0 = a[r0], a1 = a[r1];
        a[r0] = fma2(mt, a1, a0);
        a[r1] = fma2(pt, a0, a1);
    }
}

__global__ __launch_bounds__(NT, 12)
void qnn_kernel(const float* __restrict__ x,      // (B, 10)
                const float* __restrict__ w,      // (3, 10, 3)
                float* __restrict__ out)          // (B, 10)
{
    __shared__ u64 st[1024];                      // statevector exchange buffer
    __shared__ u64 ryk[2][NQ][2];                 // lifted RY consts (t,t),(-t,-t)
    __shared__ float ryt[2][2];                   // raw tangents: [l][0]=q4, [l][1]=q5
    __shared__ float2 vcol[NQ][2];                // layer-0 gate first columns
    __shared__ float2 eg[2][NQ];                  // e^{i gamma}
    __shared__ float2 ea[NQ];                     // e^{i alpha} (layer 1)
    __shared__ float2 rtab0[32], EHt[32];         // 5-bit product tables
    __shared__ float2 tA1[R], tA2[R];             // 4-bit gamma r-tables
    __shared__ u64 TIx[4][R], TIy[4][R];          // init tables (packed), by class
    __shared__ u64 TTx[4][R], TTy[4][R];          // ring-diag tables (packed)
    __shared__ float wz[2][NQ];
    __shared__ float Zs;                          // Z^2 (deferred scale)

    const int tid  = threadIdx.x;                 // 6-bit thread index T
    const int lane = tid & 31;
    const int wbit = tid >> 5;
    const int b    = blockIdx.x;

    // ---- stage 1: fused gates + ZYZ (threads 0..29) ----
    float myf = 1.f;
    if (tid < 30) {
        const int q = tid % NQ;
        const float xv  = x[b * NQ + q];
        const float phi = w[tid * 3 + 0];
        const float th  = w[tid * 3 + 1];
        const float om  = w[tid * 3 + 2];
        float s, c;   sincosf(0.5f * xv, &s, &c);
        float sh, ch; sincosf(0.5f * th, &sh, &ch);
        float sa, ca; sincosf(0.5f * (phi + om), &sa, &ca);
        float sb, cb; sincosf(0.5f * (phi - om), &sb, &cb);
        const float m00x =  ca * ch, m00y = -sa * ch;
        const float m01x = -cb * sh, m01y = -sb * sh;
        const float m10x =  cb * sh, m10y = -sb * sh;
        const float m11x =  ca * ch, m11y =  sa * ch;
        const float g00x =  m00x * c + m01x * s, g00y =  m00y * c + m01y * s;
        const float g10x =  m10x * c + m11x * s, g10y =  m10y * c + m11y * s;
        if (tid < NQ) {
            vcol[q][0] = make_float2(g00x, g00y);
            vcol[q][1] = make_float2(g10x, g10y);
        } else {
            const int l = tid / NQ - 1;
            const float cc = sqrtf(g00x * g00x + g00y * g00y);
            const float ss = sqrtf(g10x * g10x + g10y * g10y);
            float2 uA, uB;
            if (cc > 0.f) { const float iv = 1.f / cc; uA = make_float2(g00x * iv, -g00y * iv); }
            else uA = make_float2(1.f, 0.f);
            if (ss > 0.f) { const float iv = 1.f / ss; uB = make_float2(g10x * iv,  g10y * iv); }
            else uB = make_float2(1.f, 0.f);
            const float ccg = fmaxf(cc, 1e-30f);
            const float t   = ss / ccg;
            myf = ccg;
            ryk[l][q][0] = pack2(t, t);
            ryk[l][q][1] = pack2(-t, -t);
            if (q == 4) ryt[l][0] = t;
            if (q == 5) ryt[l][1] = t;
            eg[l][q] = cmul(uA, make_float2(uB.x, -uB.y));
            if (l == 0) ea[q] = cmul(uA, uB);
        }
    }
    if (wbit == 0) {                              // Z^2 from warp 0
        float Zp = myf;
#pragma unroll
        for (int o = 16; o > 0; o >>= 1) Zp *= __shfl_xor_sync(0xffffffffu, Zp, o);
        if (lane == 0) Zs = Zp * Zp;
    }
    __syncthreads();

    // ---- stage 2: 5-bit tables (warp 0) and 4-bit tables (threads 32..47) ----
    if (tid < 32) {
        const int h = tid;
        float2 v = vcol[4][h & 1];
        v = cmul(v, vcol[3][(h >> 1) & 1]);
        v = cmul(v, vcol[2][(h >> 2) & 1]);
        v = cmul(v, vcol[1][(h >> 3) & 1]);
        v = cmul(v, vcol[0][(h >> 4) & 1]);
        rtab0[h] = v;
        float2 eh = make_float2(1.f, 0.f);
#pragma unroll
        for (int j = 0; j < 5; j++)
            if ((h >> j) & 1) eh = cmul(eh, ea[4 - j]);
        EHt[h] = eh;
    } else if (tid < 48) {
        const int r = tid & 15;
        float2 a1 = make_float2(1.f, 0.f), a2 = a1;
#pragma unroll
        for (int j = 0; j < 4; j++)
            if ((r >> j) & 1) {
                a1 = cmul(a1, eg[0][3 - j]);
                a2 = cmul(a2, eg[1][3 - j]);
            }
        tA1[r] = a1;  tA2[r] = a2;
    }
    __syncthreads();

    // ---- stage 3: combined packed tables; class = (odd<<1)|w ----
    {
        const int cl = tid >> 4, r = tid & 15;
        const int Mh = (cl & 1) | ((cl & 2) ? 24 : 0);
        const int g5 = (r ^ (r << 1)) & 31;
        const float2 ti = cmul(rtab0[g5 ^ Mh], tA1[r]);
        TIx[cl][r] = pack2(ti.x, ti.x);  TIy[cl][r] = pack2(-ti.y, ti.y);
        const float2 tt = cmul(EHt[g5 ^ Mh], tA2[r]);
        TTx[cl][r] = pack2(tt.x, tt.x);  TTy[cl][r] = pack2(-tt.y, tt.y);
    }

    // ---- per-thread constants ----
    const int Ml = (lane ^ (lane >> 1)) ^ (wbit << 4);   // src low-5 bits
    float2 lo = vcol[9][Ml & 1];
    lo = cmul(lo, vcol[8][(Ml >> 1) & 1]);
    lo = cmul(lo, vcol[7][(Ml >> 2) & 1]);
    lo = cmul(lo, vcol[6][(Ml >> 3) & 1]);
    lo = cmul(lo, vcol[5][(Ml >> 4) & 1]);
    float2 loa = make_float2(1.f, 0.f), sg1 = loa, sg2 = loa;
#pragma unroll
    for (int m = 0; m < 5; m++)
        if ((Ml >> m) & 1) loa = cmul(loa, ea[9 - m]);
#pragma unroll
    for (int m = 0; m < 6; m++)
        if ((tid >> m) & 1) {
            sg1 = cmul(sg1, eg[0][9 - m]);
            sg2 = cmul(sg2, eg[1][9 - m]);
        }
    const float2 Bf = cmul(lo, sg1);
    const u64 BASE = pack2(Bf.x, Bf.y);
    const float2 SCf = cmul(loa, sg2);
    const u64 SCx = pack2(SCf.x, SCf.x), SCy = pack2(-SCf.y, SCf.y);
    const int cl = wbit | ((lane & 1) << 1);
    __syncthreads();

    const u64* TIxp = TIx[cl];  const u64* TIyp = TIy[cl];
    const u64* TTxp = TTx[cl];  const u64* TTyp = TTy[cl];

    // ---- init: layer-0 product state + ring-0 + Dgamma(1), layout A ----
    u64 a[R];
#pragma unroll
    for (int r = 0; r < R; r++) a[r] = dmul(BASE, TIxp[r], TIyp[r]);

    // ---- layers 1, 2 ----
#pragma unroll 1
    for (int l = 0; l < 2; l++) {
        // layout A: qubits 0..3 on reg bits 3..0
        ry_lift<3>(a, ryk[l][0][0], ryk[l][0][1]);
        ry_lift<2>(a, ryk[l][1][0], ryk[l][1][1]);
        ry_lift<1>(a, ryk[l][2][0], ryk[l][2][1]);
        ry_lift<0>(a, ryk[l][3][0], ryk[l][3][1]);

        // transpose A -> B (crosses warps)
        __syncthreads();
#pragma unroll
        for (int r = 0; r < R; r++) st[phys((r << 6) | tid)] = a[r];
        __syncthreads();
#pragma unroll
        for (int r = 0; r < R; r++) a[r] = st[phys((tid << 4) | r)];

        // layout B: qubits 6..9 on reg bits 3..0
        ry_lift<3>(a, ryk[l][6][0], ryk[l][6][1]);
        ry_lift<2>(a, ryk[l][7][0], ryk[l][7][1]);
        ry_lift<1>(a, ryk[l][8][0], ryk[l][8][1]);
        ry_lift<0>(a, ryk[l][9][0], ryk[l][9][1]);

        // lane gates (lifted): qubit 5 = lane bit 0, qubit 4 = lane bit 1
        {
            const float t4 = ryt[l][0], t5 = ryt[l][1];
            const float s5 = (lane & 1) ? t5 : -t5;
            const float s4 = (lane & 2) ? t4 : -t4;
            const u64 c5 = pack2(s5, s5), c4 = pack2(s4, s4);
#pragma unroll
            for (int r = 0; r < R; r++) {
                const u64 p = __shfl_xor_sync(0xffffffffu, a[r], 1);
                a[r] = fma2(c5, p, a[r]);
            }
#pragma unroll
            for (int r = 0; r < R; r++) {
                const u64 p = __shfl_xor_sync(0xffffffffu, a[r], 2);
                a[r] = fma2(c4, p, a[r]);
            }
        }

        if (l == 0) {
            // ring gather with Dalpha(1)[src] * Dgamma(2)[dst] fused
            __syncthreads();
#pragma unroll
            for (int r = 0; r < R; r++) st[phys((tid << 4) | r)] = a[r];
            __syncthreads();
            const int cc = (tid & 1) ? 0x300 : 0;
#pragma unroll
            for (int r = 0; r < R; r++) {
                const int j = (r << 6) | tid;
                const int src = j ^ (j >> 1) ^ cc;
                a[r] = dmul(dmul(st[phys(src)], TTxp[r], TTyp[r]), SCx, SCy);
            }
        }
        // layer 2: Dalpha(2) dropped (diagonal before measurement)
    }

    // ---- readout in layout B, final ring folded into parity signs ----
    float T = 0.f, P0 = 0.f, P1 = 0.f, P2 = 0.f, P3 = 0.f;
#pragma unroll
    for (int r = 0; r < R; r++) {
        float xx, yy; unpack2(mul2(a[r], a[r]), xx, yy);
        const float p = xx + yy;
        T  += p;
        P0 += (__popc(r)      & 1) ? -p : p;
        P1 += (__popc(r >> 1) & 1) ? -p : p;
        P2 += (__popc(r >> 2) & 1) ? -p : p;
        P3 += ((r >> 3)       & 1) ? -p : p;
    }
    const int pL = __popc(lane) & 1;
    const int sA = pL ^ wbit;
    float z[NQ];
    z[9] = sA ? -P0 : P0;
    z[8] = sA ? -P1 : P1;
    z[7] = sA ? -P2 : P2;
    z[6] = sA ? -P3 : P3;
    z[5] = sA ? -T  : T;
    z[4] = ((__popc(lane >> 1) & 1) ^ wbit) ? -T : T;
    z[3] = ((__popc(lane >> 2) & 1) ^ wbit) ? -T : T;
    z[2] = ((__popc(lane >> 3) & 1) ^ wbit) ? -T : T;
    z[1] = (((lane >> 4) & 1)       ^ wbit) ? -T : T;
    z[0] = pL ? -P0 : P0;

#pragma unroll
    for (int q = 0; q < NQ; q++) {
#pragma unroll
        for (int o = 16; o > 0; o >>= 1)
            z[q] += __shfl_xor_sync(0xffffffffu, z[q], o);
    }
    if (lane == 0) {
#pragma unroll
        for (int q = 0; q < NQ; q++) wz[wbit][q] = z[q];
    }
    __syncthreads();
    if (tid < NQ) out[b * NQ + tid] = (wz[0][tid] + wz[1][tid]) * Zs;
}

extern "C" void kernel_launch(void* const* d_in, const int* in_sizes, int n_in,
                              void* d_out, int out_size)
{
    const float* x = (const float*)d_in[0];       // (B, 10) float32
    const float* w = (const float*)d_in[1];       // (3, 10, 3) float32
    float* out = (float*)d_out;                   // (B, 10) float32
    const int B = in_sizes[0] / NQ;
    qnn_kernel<<<B, NT>>>(x, w, out);
}

// round 11
// speedup vs baseline: 1.3825x; 1.3825x over previous
#include <cuda_runtime.h>

#define NQ 10
#define NT 64            // 2 independent warps per CTA, 1 batch element per warp
#define R  32            // amplitudes per thread (5 register bits)

typedef unsigned long long u64;

// ---- packed f32x2 helpers (sm_103a) ----
__device__ __forceinline__ u64 pack2(float x, float y) {
    u64 r; asm("mov.b64 %0, {%1,%2};" : "=l"(r) : "f"(x), "f"(y)); return r;
}
__device__ __forceinline__ void unpack2(u64 v, float& x, float& y) {
    asm("mov.b64 {%0,%1}, %2;" : "=f"(x), "=f"(y) : "l"(v));
}
__device__ __forceinline__ u64 swap2(u64 v) {
    float x, y; unpack2(v, x, y); return pack2(y, x);
}
__device__ __forceinline__ u64 fma2(u64 a, u64 b, u64 c) {
    u64 d; asm("fma.rn.f32x2 %0, %1, %2, %3;" : "=l"(d) : "l"(a), "l"(b), "l"(c)); return d;
}
__device__ __forceinline__ u64 mul2(u64 a, u64 b) {
    u64 d; asm("mul.rn.f32x2 %0, %1, %2;" : "=l"(d) : "l"(a), "l"(b)); return d;
}
__device__ __forceinline__ float2 cmul(float2 a, float2 b) {
    return make_float2(a.x * b.x - a.y * b.y, a.x * b.y + a.y * b.x);
}
// amp *= m, with m pre-packed as mxx=(m.x,m.x), myy=(-m.y,m.y)
__device__ __forceinline__ u64 dmul(u64 amp, u64 mxx, u64 myy) {
    return fma2(mxx, amp, mul2(myy, swap2(amp)));
}
// XOR swizzle on a 1024-u64 warp-private region (proven conflict-free R2-R9)
__device__ __forceinline__ int phys(int i) { return i ^ ((i >> 5) & 31); }

// Lifted RY on register-bit P: n0 = a0 - t*a1 ; n1 = t*a0 + a1 (scale deferred)
template<int P>
__device__ __forceinline__ void ry_lift(u64* a, u64 pt, u64 mt)
{
#pragma unroll
    for (int k = 0; k < 16; k++) {
        const int r0 = ((k >> P) << (P + 1)) | (k & ((1 << P) - 1));
        const int r1 = r0 | (1 << P);
        const u64 a0 = a[r0], a1 = a[r1];
        a[r0] = fma2(mt, a1, a0);
        a[r1] = fma2(pt, a0, a1);
    }
}

__device__ __forceinline__ float2 shfl_c(float2 v, int src) {
    return make_float2(__shfl_sync(0xffffffffu, v.x, src),
                       __shfl_sync(0xffffffffu, v.y, src));
}

__global__ __launch_bounds__(NT, 10)
void qnn_kernel(const float* __restrict__ x,      // (B, 10)
                const float* __restrict__ w,      // (3, 10, 3)
                float* __restrict__ out)          // (B, 10)
{
    __shared__ u64 st[2][1024];                   // per-warp exchange buffer
    __shared__ u64 ryk[2][2][NQ][2];              // [warp][layer][q] lifted RY consts
    __shared__ float2 vcol[2][NQ][2];             // layer-0 gate first columns
    __shared__ float2 eg[2][2][NQ];               // e^{i gamma}
    __shared__ float2 ea[2][NQ];                  // e^{i alpha} (layer 1)
    __shared__ u64 TIx[2][2][R], TIy[2][2][R];    // init tables, by [warp][parity]
    __shared__ u64 TTx[2][2][R], TTy[2][2][R];    // ring-diag tables

    const int lane = threadIdx.x & 31;
    const int wid  = threadIdx.x >> 5;
    const int b    = blockIdx.x * 2 + wid;

    // ---- stage 1: fused gates + ZYZ (lanes 0..29 of each warp) ----
    float myf = 1.f;                              // deferred lifted-scale factor
    if (lane < 30) {
        const int q = lane % NQ;
        const float xv  = x[b * NQ + q];
        const float phi = w[lane * 3 + 0];
        const float th  = w[lane * 3 + 1];
        const float om  = w[lane * 3 + 2];
        float s, c;   sincosf(0.5f * xv, &s, &c);
        float sh, ch; sincosf(0.5f * th, &sh, &ch);
        float sa, ca; sincosf(0.5f * (phi + om), &sa, &ca);
        float sb, cb; sincosf(0.5f * (phi - om), &sb, &cb);
        const float m00x =  ca * ch, m00y = -sa * ch;
        const float m01x = -cb * sh, m01y = -sb * sh;
        const float m10x =  cb * sh, m10y = -sb * sh;
        const float m11x =  ca * ch, m11y =  sa * ch;
        const float g00x =  m00x * c + m01x * s, g00y =  m00y * c + m01y * s;
        const float g10x =  m10x * c + m11x * s, g10y =  m10y * c + m11y * s;
        if (lane < NQ) {
            vcol[wid][q][0] = make_float2(g00x, g00y);
            vcol[wid][q][1] = make_float2(g10x, g10y);
        } else {
            const int l = lane / NQ - 1;
            const float cc = sqrtf(g00x * g00x + g00y * g00y);
            const float ss = sqrtf(g10x * g10x + g10y * g10y);
            float2 uA, uB;
            if (cc > 0.f) { const float iv = 1.f / cc; uA = make_float2(g00x * iv, -g00y * iv); }
            else uA = make_float2(1.f, 0.f);
            if (ss > 0.f) { const float iv = 1.f / ss; uB = make_float2(g10x * iv,  g10y * iv); }
            else uB = make_float2(1.f, 0.f);
            const float ccg = fmaxf(cc, 1e-30f);
            const float t   = ss / ccg;
            myf = ccg;
            ryk[wid][l][q][0] = pack2(t, t);
            ryk[wid][l][q][1] = pack2(-t, -t);
            eg[wid][l][q] = cmul(uA, make_float2(uB.x, -uB.y));
            if (l == 0) ea[wid][q] = cmul(uA, uB);
        }
    }
    __syncwarp();
    float Z = myf;                                // product of 20 scale factors
#pragma unroll
    for (int o = 16; o > 0; o >>= 1) Z *= __shfl_xor_sync(0xffffffffu, Z, o);
    const float Zsq = Z * Z;

    // ---- stage 2: per-bit product tables, register-resident (entry h = lane) ----
    float2 rt0, eh, tA1v, tA2v;
    {
        const int h = lane;
        float2 v = vcol[wid][4][h & 1];
        v = cmul(v, vcol[wid][3][(h >> 1) & 1]);
        v = cmul(v, vcol[wid][2][(h >> 2) & 1]);
        v = cmul(v, vcol[wid][1][(h >> 3) & 1]);
        v = cmul(v, vcol[wid][0][(h >> 4) & 1]);
        rt0 = v;
        float2 a1 = make_float2(1.f, 0.f), a2 = a1, e = a1;
#pragma unroll
        for (int j = 0; j < 5; j++)
            if ((h >> j) & 1) {
                a1 = cmul(a1, eg[wid][0][4 - j]);
                a2 = cmul(a2, eg[wid][1][4 - j]);
                e  = cmul(e,  ea[wid][4 - j]);
            }
        tA1v = a1;  tA2v = a2;  eh = e;
    }
    __syncwarp();

    // ---- stage 3: combined packed tables via shfl (parity p = src-lane lsb) ----
    {
        const int h   = lane;
        const int sh0 = h ^ (h >> 1);
        const int sh1 = sh0 ^ 0b11000;
        const float2 r0 = shfl_c(rt0, sh0), r1 = shfl_c(rt0, sh1);
        const float2 e0 = shfl_c(eh,  sh0), e1 = shfl_c(eh,  sh1);
        const float2 ti0 = cmul(r0, tA1v), ti1 = cmul(r1, tA1v);
        const float2 tt0 = cmul(e0, tA2v), tt1 = cmul(e1, tA2v);
        TIx[wid][0][h] = pack2(ti0.x, ti0.x);  TIy[wid][0][h] = pack2(-ti0.y, ti0.y);
        TIx[wid][1][h] = pack2(ti1.x, ti1.x);  TIy[wid][1][h] = pack2(-ti1.y, ti1.y);
        TTx[wid][0][h] = pack2(tt0.x, tt0.x);  TTy[wid][0][h] = pack2(-tt0.y, tt0.y);
        TTx[wid][1][h] = pack2(tt1.x, tt1.x);  TTy[wid][1][h] = pack2(-tt1.y, tt1.y);
    }
    // ---- per-thread scalars ----
    float2 sgam1 = make_float2(1.f, 0.f), sgam2 = sgam1;
#pragma unroll
    for (int k = 0; k < 5; k++)
        if ((lane >> k) & 1) {
            sgam1 = cmul(sgam1, eg[wid][0][9 - k]);
            sgam2 = cmul(sgam2, eg[wid][1][9 - k]);
        }
    const int m0 = lane ^ (lane >> 1);
    float2 el = make_float2(1.f, 0.f);
#pragma unroll
    for (int j = 0; j < 5; j++)
        if ((m0 >> j) & 1) el = cmul(el, ea[wid][9 - j]);
    const float2 el2 = ((m0 >> 4) & 1)
        ? cmul(el, make_float2(ea[wid][5].x, -ea[wid][5].y))
        : cmul(el, ea[wid][5]);
    const float2 SL0f = cmul(el,  sgam2);
    const float2 SL1f = cmul(el2, sgam2);
    const u64 SLx0 = pack2(SL0f.x, SL0f.x), SLy0 = pack2(-SL0f.y, SL0f.y);
    const u64 SLx1 = pack2(SL1f.x, SL1f.x), SLy1 = pack2(-SL1f.y, SL1f.y);
    // init lane scalars (layer-0 lane part at the two src_lo values, sgam1 folded)
    float2 lp = vcol[wid][9][m0 & 1];
    lp = cmul(lp, vcol[wid][8][(m0 >> 1) & 1]);
    lp = cmul(lp, vcol[wid][7][(m0 >> 2) & 1]);
    lp = cmul(lp, vcol[wid][6][(m0 >> 3) & 1]);
    const int b4 = (m0 >> 4) & 1;
    const float2 l0 = cmul(cmul(lp, vcol[wid][5][b4]),     sgam1);
    const float2 l1 = cmul(cmul(lp, vcol[wid][5][1 - b4]), sgam1);
    const u64 ls0 = pack2(l0.x, l0.y), ls1 = pack2(l1.x, l1.y);
    __syncwarp();

    const int pl2 = lane & 1;
    const u64* TIxp = TIx[wid][pl2];  const u64* TIyp = TIy[wid][pl2];
    const u64* TTxp = TTx[wid][pl2];  const u64* TTyp = TTy[wid][pl2];
    u64* S = st[wid];

    // ---- init: layer-0 product state + ring-0 + Dgamma(1), layout A ----
    u64 a[R];
#pragma unroll
    for (int r = 0; r < R; r++)
        a[r] = dmul((r & 1) ? ls1 : ls0, TIxp[r], TIyp[r]);

    // ---- layers 1, 2 (lifted RY; diagonals pre-combined) ----
#pragma unroll 1
    for (int l = 0; l < 2; l++) {
        // layout A: qubits 0..4 on reg bits 4..0
        ry_lift<4>(a, ryk[wid][l][0][0], ryk[wid][l][0][1]);
        ry_lift<3>(a, ryk[wid][l][1][0], ryk[wid][l][1][1]);
        ry_lift<2>(a, ryk[wid][l][2][0], ryk[wid][l][2][1]);
        ry_lift<1>(a, ryk[wid][l][3][0], ryk[wid][l][3][1]);
        ry_lift<0>(a, ryk[wid][l][4][0], ryk[wid][l][4][1]);

        // transpose A -> B (warp-private)
#pragma unroll
        for (int r = 0; r < R; r++) S[phys((r << 5) | lane)] = a[r];
        __syncwarp();
#pragma unroll
        for (int r = 0; r < R; r++) a[r] = st[wid][phys((lane << 5) | r)];
        __syncwarp();

        // layout B: qubits 5..9 on reg bits 4..0
        ry_lift<4>(a, ryk[wid][l][5][0], ryk[wid][l][5][1]);
        ry_lift<3>(a, ryk[wid][l][6][0], ryk[wid][l][6][1]);
        ry_lift<2>(a, ryk[wid][l][7][0], ryk[wid][l][7][1]);
        ry_lift<1>(a, ryk[wid][l][8][0], ryk[wid][l][8][1]);
        ry_lift<0>(a, ryk[wid][l][9][0], ryk[wid][l][9][1]);

        if (l == 0) {
            // ring gather with Dalpha(1)[src] * Dgamma(2)[dst] fused
#pragma unroll
            for (int r = 0; r < R; r++) S[phys((lane << 5) | r)] = a[r];
            __syncwarp();
#pragma unroll
            for (int r = 0; r < R; r++) {
                const int j = (r << 5) | lane;
                int src = j ^ (j >> 1);
                if (j & 1) src ^= 0x300;
                const u64 raw = S[phys(src)];
                const u64 t1  = dmul(raw, TTxp[r], TTyp[r]);
                a[r] = (r & 1) ? dmul(t1, SLx1, SLy1) : dmul(t1, SLx0, SLy0);
            }
            __syncwarp();
        }
        // layer 2: Dalpha(2) dropped (diagonal before measurement)
    }

    // ---- readout in layout B, final ring folded into parity signs ----
    float T = 0.f, P0 = 0.f, P1 = 0.f, P2 = 0.f, P3 = 0.f, P4 = 0.f;
#pragma unroll
    for (int r = 0; r < R; r++) {
        float xx, yy; unpack2(mul2(a[r], a[r]), xx, yy);
        const float p = xx + yy;
        T  += p;
        P0 += (__popc(r)      & 1) ? -p : p;
        P1 += (__popc(r >> 1) & 1) ? -p : p;
        P2 += (__popc(r >> 2) & 1) ? -p : p;
        P3 += (__popc(r >> 3) & 1) ? -p : p;
        P4 += (__popc(r >> 4) & 1) ? -p : p;
    }

    const int pl = __popc(lane) & 1;
    float z[NQ];
    z[9] = pl ? -P0 : P0;
    z[8] = pl ? -P1 : P1;
    z[7] = pl ? -P2 : P2;
    z[6] = pl ? -P3 : P3;
    z[5] = pl ? -P4 : P4;
    z[4] = pl ? -T  : T;
    z[3] = (__popc(lane >> 1) & 1) ? -T : T;
    z[2] = (__popc(lane >> 2) & 1) ? -T : T;
    z[1] = (__popc(lane >> 3) & 1) ? -T : T;
    z[0] = (__popc(lane & 0xF) & 1) ? -P0 : P0;

#pragma unroll
    for (int q = 0; q < NQ; q++) {
#pragma unroll
        for (int o = 16; o > 0; o >>= 1)
            z[q] += __shfl_xor_sync(0xffffffffu, z[q], o);
    }
    if (lane == 0) {
#pragma unroll
        for (int q = 0; q < NQ; q++) out[b * NQ + q] = z[q] * Zsq;
    }
}

extern "C" void kernel_launch(void* const* d_in, const int* in_sizes, int n_in,
                              void* d_out, int out_size)
{
    const float* x = (const float*)d_in[0];       // (B, 10) float32
    const float* w = (const float*)d_in[1];       // (3, 10, 3) float32
    float* out = (float*)d_out;                   // (B, 10) float32
    const int B = in_sizes[0] / NQ;
    qnn_kernel<<<B / 2, NT>>>(x, w, out);
}